// round 1
// baseline (speedup 1.0000x reference)
#include <cuda_runtime.h>
#include <math.h>

#define N 16384
#define D 1024
#define TILE 128   // 128x128 gram tiles, 128 tile-rows/cols

// Scratch (static __device__ globals — allocation-free per harness rules)
__device__ float    g_nfeats[(size_t)N * D];   // normalized features, 67 MB
__device__ unsigned g_rowmax[N];               // order-encoded per-row max dot

// ---- order-preserving float<->uint encoding (enables native atomicMax) ----
__device__ __forceinline__ unsigned f2key(float f) {
    unsigned u = __float_as_uint(f);
    return (u & 0x80000000u) ? ~u : (u | 0x80000000u);
}
__device__ __forceinline__ float key2f(unsigned k) {
    unsigned u = (k & 0x80000000u) ? (k & 0x7FFFFFFFu) : ~k;
    return __uint_as_float(u);
}

// ---- kernel 1: L2-normalize rows (one block per row) ----
__global__ void normalize_kernel(const float* __restrict__ in) {
    int row = blockIdx.x;
    const float4* src = (const float4*)(in + (size_t)row * D);
    float4 v = src[threadIdx.x];                       // 256 thr * 4 = 1024
    float s = v.x * v.x + v.y * v.y + v.z * v.z + v.w * v.w;
    __shared__ float red[8];
    #pragma unroll
    for (int o = 16; o > 0; o >>= 1) s += __shfl_xor_sync(0xffffffffu, s, o);
    if ((threadIdx.x & 31) == 0) red[threadIdx.x >> 5] = s;
    __syncthreads();
    if (threadIdx.x < 8) {
        float t = red[threadIdx.x];
        #pragma unroll
        for (int o = 4; o > 0; o >>= 1) t += __shfl_xor_sync(0xffu, t, o);
        if (threadIdx.x == 0) red[0] = t;
    }
    __syncthreads();
    float norm  = sqrtf(red[0]);
    float scale = 1.0f / fmaxf(norm, 1e-12f);
    v.x *= scale; v.y *= scale; v.z *= scale; v.w *= scale;
    ((float4*)(g_nfeats + (size_t)row * D))[threadIdx.x] = v;
}

// ---- kernel 2: init row maxes ----
__global__ void init_rowmax_kernel() {
    int i = blockIdx.x * blockDim.x + threadIdx.x;
    if (i < N) g_rowmax[i] = 0u;   // key floor (decodes below any real float)
}

// ---- kernel 3: symmetric tiled Gram with row-max epilogue ----
// Grid (128,128); only tiles with ti <= tj compute. Each tile updates
// rowmax for its row block (max over cols) AND its col block (max over rows,
// using S[j,i] = S[i,j]).
__global__ void __launch_bounds__(256) gram_max_kernel() {
    int tj = blockIdx.x;   // col tile
    int ti = blockIdx.y;   // row tile
    if (ti > tj) return;

    const int rowBase = ti * TILE;
    const int colBase = tj * TILE;

    __shared__ float As[8][TILE];
    __shared__ float Bs[8][TILE];
    __shared__ unsigned rmax[TILE], cmax[TILE];

    int tid = threadIdx.x;
    if (tid < TILE) { rmax[tid] = 0u; cmax[tid] = 0u; }

    int tx = tid & 15;     // 0..15
    int ty = tid >> 4;     // 0..15

    float acc[8][8];
    #pragma unroll
    for (int i = 0; i < 8; i++)
        #pragma unroll
        for (int j = 0; j < 8; j++) acc[i][j] = 0.0f;

    // loader mapping: thread -> (row 0..127, k-quad 0 or 4)
    int lrow = tid >> 1;
    int lk4  = (tid & 1) * 4;
    const float* aptr = g_nfeats + (size_t)(rowBase + lrow) * D + lk4;
    const float* bptr = g_nfeats + (size_t)(colBase + lrow) * D + lk4;

    for (int k0 = 0; k0 < D; k0 += 8) {
        float4 av = *(const float4*)(aptr + k0);
        float4 bv = *(const float4*)(bptr + k0);
        __syncthreads();   // previous iter's compute done (also covers rmax init)
        As[lk4 + 0][lrow] = av.x; As[lk4 + 1][lrow] = av.y;
        As[lk4 + 2][lrow] = av.z; As[lk4 + 3][lrow] = av.w;
        Bs[lk4 + 0][lrow] = bv.x; Bs[lk4 + 1][lrow] = bv.y;
        Bs[lk4 + 2][lrow] = bv.z; Bs[lk4 + 3][lrow] = bv.w;
        __syncthreads();

        #pragma unroll
        for (int k = 0; k < 8; k++) {
            float ra[8], rb[8];
            *(float4*)&ra[0] = *(const float4*)&As[k][ty * 4];
            *(float4*)&ra[4] = *(const float4*)&As[k][64 + ty * 4];
            *(float4*)&rb[0] = *(const float4*)&Bs[k][tx * 4];
            *(float4*)&rb[4] = *(const float4*)&Bs[k][64 + tx * 4];
            #pragma unroll
            for (int i = 0; i < 8; i++)
                #pragma unroll
                for (int j = 0; j < 8; j++)
                    acc[i][j] = fmaf(ra[i], rb[j], acc[i][j]);
        }
    }

    // fragment -> tile coordinates (split-quad layout)
    int rowsIdx[8], colsIdx[8];
    #pragma unroll
    for (int i = 0; i < 8; i++) {
        rowsIdx[i] = (i < 4) ? (ty * 4 + i) : (64 + ty * 4 + (i - 4));
        colsIdx[i] = (i < 4) ? (tx * 4 + i) : (64 + tx * 4 + (i - 4));
    }

    // per-thread row maxes (exclude diagonal), reduce into shared
    #pragma unroll
    for (int i = 0; i < 8; i++) {
        int gi = rowBase + rowsIdx[i];
        float m = -3.0f;   // below any cosine in [-1,1]
        #pragma unroll
        for (int j = 0; j < 8; j++) {
            int gj = colBase + colsIdx[j];
            float v = (gi == gj) ? -3.0f : acc[i][j];
            m = fmaxf(m, v);
        }
        atomicMax(&rmax[rowsIdx[i]], f2key(m));
    }
    // per-thread col maxes (symmetric contribution)
    #pragma unroll
    for (int j = 0; j < 8; j++) {
        int gj = colBase + colsIdx[j];
        float m = -3.0f;
        #pragma unroll
        for (int i = 0; i < 8; i++) {
            int gi = rowBase + rowsIdx[i];
            float v = (gi == gj) ? -3.0f : acc[i][j];
            m = fmaxf(m, v);
        }
        atomicMax(&cmax[colsIdx[j]], f2key(m));
    }
    __syncthreads();

    if (tid < TILE) {
        atomicMax(&g_rowmax[rowBase + tid], rmax[tid]);
        if (ti != tj)
            atomicMax(&g_rowmax[colBase + tid], cmax[tid]);
    }
}

// ---- kernel 4: loss = -mean(log(sqrt(2 - 2*maxdot) + eps)) ----
__global__ void loss_kernel(float* __restrict__ out) {
    int tid = threadIdx.x;
    float s = 0.0f;
    for (int i = tid; i < N; i += blockDim.x) {
        float md   = key2f(g_rowmax[i]);
        float d2   = fmaxf(2.0f - 2.0f * md, 0.0f);
        float dist = sqrtf(d2);
        s += logf(dist + 1e-8f);
    }
    __shared__ float red[32];
    #pragma unroll
    for (int o = 16; o > 0; o >>= 1) s += __shfl_xor_sync(0xffffffffu, s, o);
    if ((tid & 31) == 0) red[tid >> 5] = s;
    __syncthreads();
    if (tid < 32) {
        float t = red[tid];
        #pragma unroll
        for (int o = 16; o > 0; o >>= 1) t += __shfl_xor_sync(0xffffffffu, t, o);
        if (tid == 0) out[0] = -t / (float)N;
    }
}

extern "C" void kernel_launch(void* const* d_in, const int* in_sizes, int n_in,
                              void* d_out, int out_size) {
    const float* feats = (const float*)d_in[0];
    float* out = (float*)d_out;

    normalize_kernel<<<N, 256>>>(feats);
    init_rowmax_kernel<<<(N + 1023) / 1024, 1024>>>();
    dim3 grid(N / TILE, N / TILE);   // (128,128); lower triangle exits early
    gram_max_kernel<<<grid, 256>>>();
    loss_kernel<<<1, 1024>>>(out);
}

// round 4
// speedup vs baseline: 8.9365x; 8.9365x over previous
#include <cuda_runtime.h>
#include <cuda_bf16.h>
#include <math.h>
#include <stdint.h>

#define N 16384
#define D 1024
#define BT 128            // block tile (M and N)
#define BK 64             // k-chunk in bf16 (=128 bytes per row)
#define NKT (D / BK)      // 16 k-iterations

// ---------------- device globals (allocation-free scratch) ----------------
__device__ __align__(128) __nv_bfloat16 g_bf[(size_t)N * D];   // normalized, bf16
__device__ unsigned g_rowmax[N];

// ---- order-preserving float<->uint keys (native atomicMax on floats) ----
__device__ __forceinline__ unsigned f2key(float f) {
    unsigned u = __float_as_uint(f);
    return (u & 0x80000000u) ? ~u : (u | 0x80000000u);
}
__device__ __forceinline__ float key2f(unsigned k) {
    unsigned u = (k & 0x80000000u) ? (k & 0x7FFFFFFFu) : ~k;
    return __uint_as_float(u);
}

__device__ __forceinline__ uint32_t smem_u32(const void* p) {
    uint32_t a;
    asm("{ .reg .u64 t; cvta.to.shared.u64 t, %1; cvt.u32.u64 %0, t; }" : "=r"(a) : "l"(p));
    return a;
}
#define SW128(off) ((off) ^ (((off) >> 3) & 0x70))

__device__ __forceinline__ void cp16(uint32_t dst, const void* src) {
    asm volatile("cp.async.cg.shared.global [%0], [%1], 16;" :: "r"(dst), "l"(src));
}

__device__ __forceinline__ void ldm_x4(uint32_t* r, uint32_t addr) {
    asm volatile("ldmatrix.sync.aligned.m8n8.x4.shared.b16 {%0,%1,%2,%3}, [%4];"
                 : "=r"(r[0]), "=r"(r[1]), "=r"(r[2]), "=r"(r[3]) : "r"(addr));
}

__device__ __forceinline__ void mma16816(float* c, const uint32_t* a, const uint32_t* b) {
    asm volatile(
        "mma.sync.aligned.m16n8k16.row.col.f32.bf16.bf16.f32 "
        "{%0,%1,%2,%3}, {%4,%5,%6,%7}, {%8,%9}, {%0,%1,%2,%3};"
        : "+f"(c[0]), "+f"(c[1]), "+f"(c[2]), "+f"(c[3])
        : "r"(a[0]), "r"(a[1]), "r"(a[2]), "r"(a[3]), "r"(b[0]), "r"(b[1]));
}

// ---------------- kernel 1: L2-normalize rows -> bf16 ----------------
__global__ void normalize_kernel(const float* __restrict__ in) {
    int row = blockIdx.x;
    float4 v = ((const float4*)(in + (size_t)row * D))[threadIdx.x];   // 256 thr
    float s = v.x * v.x + v.y * v.y + v.z * v.z + v.w * v.w;
    __shared__ float red[8];
    #pragma unroll
    for (int o = 16; o > 0; o >>= 1) s += __shfl_xor_sync(0xffffffffu, s, o);
    if ((threadIdx.x & 31) == 0) red[threadIdx.x >> 5] = s;
    __syncthreads();
    if (threadIdx.x < 8) {
        float t = red[threadIdx.x];
        #pragma unroll
        for (int o = 4; o > 0; o >>= 1) t += __shfl_xor_sync(0xffu, t, o);
        if (threadIdx.x == 0) red[0] = t;
    }
    __syncthreads();
    float scale = 1.0f / fmaxf(sqrtf(red[0]), 1e-12f);
    __nv_bfloat162 p0 = __nv_bfloat162(__float2bfloat16(v.x * scale), __float2bfloat16(v.y * scale));
    __nv_bfloat162 p1 = __nv_bfloat162(__float2bfloat16(v.z * scale), __float2bfloat16(v.w * scale));
    size_t base = (size_t)row * D + threadIdx.x * 4;
    ((__nv_bfloat162*)(g_bf + base))[0] = p0;
    ((__nv_bfloat162*)(g_bf + base))[1] = p1;
}

__global__ void init_rowmax_kernel() {
    int i = blockIdx.x * blockDim.x + threadIdx.x;
    if (i < N) g_rowmax[i] = 0u;
}

// ---------------- kernel 2: gram tile + row/col max (mma.sync bf16) ----------------
// smem: 2 stages x (A 16KB + B 16KB) = 64KB dynamic; rmax/cmax static.
#define STAGE_BYTES 32768
#define A_OFF 0
#define B_OFF 16384
#define SMEM_TOTAL (2 * STAGE_BYTES)

__global__ void __launch_bounds__(256, 2) gram_kernel() {
    int tj = blockIdx.x;        // col tile
    int ti = blockIdx.y;        // row tile
    if (ti > tj) return;        // upper triangle only; symmetry handled in epilogue

    extern __shared__ char smem[];
    __shared__ unsigned s_rmax[BT], s_cmax[BT];

    const int rowBase = ti * BT;
    const int colBase = tj * BT;
    const int tid  = threadIdx.x;
    const int lane = tid & 31;
    const int wid  = tid >> 5;       // 0..7
    const int wm   = wid & 3;        // 4 m-warps: rows wm*32..+31
    const int wn   = wid >> 2;       // 2 n-warps: cols wn*64..+63

    if (tid < BT) { s_rmax[tid] = 0u; s_cmax[tid] = 0u; }

    uint32_t sb = smem_u32(smem);

    // ---- stage loader: 32KB via 2048 cp.async of 16B ----
    auto load_stage = [&](int kt, int s) {
        int k0 = kt * BK;                                  // bf16 offset
        uint32_t base = sb + s * STAGE_BYTES;
        #pragma unroll
        for (int it = 0; it < 4; it++) {
            int i = tid + it * 256;                        // 0..1023
            int r = i >> 3, seg = i & 7;
            uint32_t off = SW128(r * 128 + seg * 16);
            const __nv_bfloat16* gA = g_bf + (size_t)(rowBase + r) * D + k0 + seg * 8;
            const __nv_bfloat16* gB = g_bf + (size_t)(colBase + r) * D + k0 + seg * 8;
            cp16(base + A_OFF + off, gA);
            cp16(base + B_OFF + off, gB);
        }
        asm volatile("cp.async.commit_group;" ::: "memory");
    };

    float acc[2][8][4];
    #pragma unroll
    for (int mf = 0; mf < 2; mf++)
        #pragma unroll
        for (int nf = 0; nf < 8; nf++)
            #pragma unroll
            for (int e = 0; e < 4; e++) acc[mf][nf][e] = 0.0f;

    // ldmatrix lane address components (row within tile, 16B column select)
    const int aRowL = (lane & 7) + ((lane >> 3) & 1) * 8;      // + m0
    const int aColS = (lane >> 4) * 16;                         // byte
    const int bRowL = (lane & 7) + (lane >> 4) * 8;            // + n0
    const int bColS = ((lane >> 3) & 1) * 16;                   // byte

    load_stage(0, 0);

    for (int kt = 0; kt < NKT; kt++) {
        int s = kt & 1;
        asm volatile("cp.async.wait_group 0;" ::: "memory");
        __syncthreads();
        if (kt + 1 < NKT) load_stage(kt + 1, s ^ 1);

        uint32_t aBase = sb + s * STAGE_BYTES + A_OFF;
        uint32_t bBase = sb + s * STAGE_BYTES + B_OFF;

        #pragma unroll
        for (int ks = 0; ks < 4; ks++) {                       // 4 x k16
            int kb = ks * 32;                                  // byte col
            uint32_t a[2][4], b[4][4];
            #pragma unroll
            for (int mf = 0; mf < 2; mf++) {
                int r = wm * 32 + mf * 16 + aRowL;
                ldm_x4(a[mf], aBase + SW128(r * 128 + kb + aColS));
            }
            #pragma unroll
            for (int np = 0; np < 4; np++) {                   // 4 pairs of n-frags
                int r = wn * 64 + np * 16 + bRowL;
                ldm_x4(b[np], bBase + SW128(r * 128 + kb + bColS));
            }
            #pragma unroll
            for (int mf = 0; mf < 2; mf++)
                #pragma unroll
                for (int np = 0; np < 4; np++) {
                    mma16816(acc[mf][2 * np],     a[mf], &b[np][0]);
                    mma16816(acc[mf][2 * np + 1], a[mf], &b[np][2]);
                }
        }
        __syncthreads();
    }

    // ---- diagonal mask (only diagonal tiles can hit it) ----
    const int g  = lane >> 2;        // 0..7
    const int cq = lane & 3;         // 0..3
    if (ti == tj) {
        #pragma unroll
        for (int mf = 0; mf < 2; mf++)
            #pragma unroll
            for (int nf = 0; nf < 8; nf++)
                #pragma unroll
                for (int e = 0; e < 4; e++) {
                    int row = wm * 32 + mf * 16 + g + (e >> 1) * 8;
                    int col = wn * 64 + nf * 8 + 2 * cq + (e & 1);
                    if (row == col) acc[mf][nf][e] = -3.0f;
                }
    }

    // ---- row maxes: reduce over cols (shuffle over cq), then smem atomic ----
    #pragma unroll
    for (int mf = 0; mf < 2; mf++)
        #pragma unroll
        for (int h = 0; h < 2; h++) {
            float m = -3.0f;
            #pragma unroll
            for (int nf = 0; nf < 8; nf++) {
                m = fmaxf(m, acc[mf][nf][2 * h]);
                m = fmaxf(m, acc[mf][nf][2 * h + 1]);
            }
            m = fmaxf(m, __shfl_xor_sync(0xffffffffu, m, 1));
            m = fmaxf(m, __shfl_xor_sync(0xffffffffu, m, 2));
            if (cq == 0) atomicMax(&s_rmax[wm * 32 + mf * 16 + h * 8 + g], f2key(m));
        }

    // ---- col maxes: reduce over rows (shuffle over g), then smem atomic ----
    #pragma unroll
    for (int nf = 0; nf < 8; nf++)
        #pragma unroll
        for (int e = 0; e < 2; e++) {
            float m = -3.0f;
            #pragma unroll
            for (int mf = 0; mf < 2; mf++) {
                m = fmaxf(m, acc[mf][nf][e]);
                m = fmaxf(m, acc[mf][nf][2 + e]);
            }
            m = fmaxf(m, __shfl_xor_sync(0xffffffffu, m, 4));
            m = fmaxf(m, __shfl_xor_sync(0xffffffffu, m, 8));
            m = fmaxf(m, __shfl_xor_sync(0xffffffffu, m, 16));
            if (g == 0) atomicMax(&s_cmax[wn * 64 + nf * 8 + 2 * cq + e], f2key(m));
        }
    __syncthreads();

    if (tid < BT) {
        atomicMax(&g_rowmax[rowBase + tid], s_rmax[tid]);
    } else {
        int c = tid - BT;
        if (ti != tj) atomicMax(&g_rowmax[colBase + c], s_cmax[c]);
    }
}

// ---------------- kernel 3: loss ----------------
__global__ void loss_kernel(float* __restrict__ out) {
    int tid = threadIdx.x;
    float s = 0.0f;
    for (int i = tid; i < N; i += blockDim.x) {
        float md = key2f(g_rowmax[i]);
        float d2 = fmaxf(2.0f - 2.0f * md, 0.0f);
        s += logf(sqrtf(d2) + 1e-8f);
    }
    __shared__ float red[32];
    #pragma unroll
    for (int o = 16; o > 0; o >>= 1) s += __shfl_xor_sync(0xffffffffu, s, o);
    if ((tid & 31) == 0) red[tid >> 5] = s;
    __syncthreads();
    if (tid < 32) {
        float t = red[tid];
        #pragma unroll
        for (int o = 16; o > 0; o >>= 1) t += __shfl_xor_sync(0xffffffffu, t, o);
        if (tid == 0) out[0] = -t / (float)N;
    }
}

// ---------------- launch ----------------
extern "C" void kernel_launch(void* const* d_in, const int* in_sizes, int n_in,
                              void* d_out, int out_size) {
    const float* feats = (const float*)d_in[0];
    float* out = (float*)d_out;

    cudaFuncSetAttribute(gram_kernel, cudaFuncAttributeMaxDynamicSharedMemorySize, SMEM_TOTAL);

    normalize_kernel<<<N, 256>>>(feats);
    init_rowmax_kernel<<<(N + 1023) / 1024, 1024>>>();
    dim3 grid(N / BT, N / BT);          // (128,128); ti>tj exits immediately
    gram_kernel<<<grid, 256, SMEM_TOTAL>>>();
    loss_kernel<<<1, 1024>>>(out);
}